// round 2
// baseline (speedup 1.0000x reference)
#include <cuda_runtime.h>
#include <math.h>

#define N_NODES 50000
#define N_EDGES 800000
#define C1 256
#define C2 128

// ---------------- scratch (allocation-free: __device__ globals) ----------------
__device__ int   g_is64;                 // 1 if edge_index is int64, 0 if int32
__device__ float g_deg [N_NODES];
__device__ float g_dinv[N_NODES];
__device__ float g_xw1 [N_NODES * C1];   // x @ W1          (51.2 MB)
__device__ float g_agg1[N_NODES * C1];   // layer1 agg -> h (51.2 MB, reused in place)
__device__ float g_xw2 [N_NODES * C2];   // h @ W2, later reused for p (25.6 MB)
__device__ float g_agg2[N_NODES * C2];   // layer2 agg -> z (25.6 MB, reused in place)

// ---------------- dtype probe: int64 vs int32 edge_index ----------------
// Reads only the first 128 bytes (safe under both layouts). If the buffer is
// int32, an int64 view combines two random values < 50000 -> hi word nonzero.
__global__ void detect_kernel(const void* __restrict__ ei) {
    if (threadIdx.x == 0 && blockIdx.x == 0) {
        const long long* p = (const long long*)ei;
        int ok64 = 1;
        #pragma unroll
        for (int i = 0; i < 16; i++) {
            long long v = p[i];
            if (v < 0 || v >= N_NODES) ok64 = 0;
        }
        g_is64 = ok64;
    }
}

__device__ __forceinline__ void load_edge(const void* __restrict__ ei, int e,
                                          int& s, int& d) {
    if (g_is64) {
        const long long* p = (const long long*)ei;
        s = (int)p[e];
        d = (int)p[N_EDGES + e];
    } else {
        const int* p = (const int*)ei;
        s = p[e];
        d = p[N_EDGES + e];
    }
    // defensive clamp: never fault on unexpected data
    if ((unsigned)s >= N_NODES) s = 0;
    if ((unsigned)d >= N_NODES) d = 0;
}

// ---------------- init: deg = 1 (self loop), zero both agg buffers ----------------
__global__ void init_kernel(float* __restrict__ deg,
                            float* __restrict__ agg1,
                            float* __restrict__ agg2) {
    int idx = blockIdx.x * blockDim.x + threadIdx.x;   // over float4 units
    const int T1 = N_NODES * C1 / 4;   // 3,200,000
    const int T2 = N_NODES * C2 / 4;   // 1,600,000
    const int TD = N_NODES / 4;        // 12,500 exact
    float4 z4 = make_float4(0.f, 0.f, 0.f, 0.f);
    if (idx < T1) reinterpret_cast<float4*>(agg1)[idx] = z4;
    if (idx < T2) reinterpret_cast<float4*>(agg2)[idx] = z4;
    if (idx < TD) reinterpret_cast<float4*>(deg)[idx] = make_float4(1.f, 1.f, 1.f, 1.f);
}

// ---------------- degree histogram over dst ----------------
__global__ void deg_kernel(const void* __restrict__ ei, float* __restrict__ deg) {
    int e = blockIdx.x * blockDim.x + threadIdx.x;
    if (e < N_EDGES) {
        int s, d;
        load_edge(ei, e, s, d);
        atomicAdd(&deg[d], 1.0f);
    }
}

__global__ void dinv_kernel(const float* __restrict__ deg, float* __restrict__ dinv) {
    int i = blockIdx.x * blockDim.x + threadIdx.x;
    if (i < N_NODES) dinv[i] = rsqrtf(deg[i]);
}

// ---------------- fp32 SGEMM: C = act(A[MxK] @ B[KxN] + bias) ----------------
// BM=BN=128, BK=8, TM=TN=8, 256 threads. act: 0 = none, 2 = ELU.
__global__ __launch_bounds__(256)
void sgemm_kernel(const float* __restrict__ A, const float* __restrict__ B,
                  const float* __restrict__ bias, float* __restrict__ C,
                  int M, int N, int K, int act) {
    __shared__ float As[8][128];
    __shared__ float Bs[8][128];

    const int bn = blockIdx.x * 128;
    const int bm = blockIdx.y * 128;
    const int tid = threadIdx.x;
    const int tx = tid & 15;          // 16 x 16 thread grid
    const int ty = tid >> 4;

    float acc[8][8];
    #pragma unroll
    for (int i = 0; i < 8; i++)
        #pragma unroll
        for (int j = 0; j < 8; j++) acc[i][j] = 0.f;

    // A tile load mapping: 128 rows x 8 k, float4 per thread along K
    const int arow = tid >> 1;
    const int acol = (tid & 1) * 4;
    const int aRowG = bm + arow;
    const bool aValid = aRowG < M;
    const float* Aptr = A + (size_t)(aValid ? aRowG : 0) * K;
    // B tile load mapping: 8 rows x 128 cols, float4 per thread along N
    const int brow = tid >> 5;
    const int bcol = (tid & 31) * 4;

    for (int k0 = 0; k0 < K; k0 += 8) {
        float4 av = aValid ? *reinterpret_cast<const float4*>(Aptr + k0 + acol)
                           : make_float4(0.f, 0.f, 0.f, 0.f);
        As[acol + 0][arow] = av.x;
        As[acol + 1][arow] = av.y;
        As[acol + 2][arow] = av.z;
        As[acol + 3][arow] = av.w;
        float4 bv = *reinterpret_cast<const float4*>(B + (size_t)(k0 + brow) * N + bn + bcol);
        *reinterpret_cast<float4*>(&Bs[brow][bcol]) = bv;
        __syncthreads();

        #pragma unroll
        for (int kk = 0; kk < 8; kk++) {
            float ar[8], br[8];
            #pragma unroll
            for (int i = 0; i < 8; i++) ar[i] = As[kk][ty * 8 + i];
            #pragma unroll
            for (int j = 0; j < 8; j++) br[j] = Bs[kk][tx * 8 + j];
            #pragma unroll
            for (int i = 0; i < 8; i++)
                #pragma unroll
                for (int j = 0; j < 8; j++)
                    acc[i][j] = fmaf(ar[i], br[j], acc[i][j]);
        }
        __syncthreads();
    }

    // epilogue
    #pragma unroll
    for (int i = 0; i < 8; i++) {
        int row = bm + ty * 8 + i;
        if (row >= M) break;
        float* Crow = C + (size_t)row * N + bn + tx * 8;
        #pragma unroll
        for (int j = 0; j < 8; j++) {
            float v = acc[i][j];
            if (bias) v += bias[bn + tx * 8 + j];
            if (act == 2) v = v > 0.f ? v : expm1f(v);   // ELU(alpha=1)
            Crow[j] = v;
        }
    }
}

// ---------------- edge aggregation: agg[dst] += xw[src] * dinv[src]*dinv[dst] ----
// One warp per edge; float4 gathers + sm_90+ float4 atomicAdd scatters (L2-resident).
template <int C4>
__global__ void edge_agg_kernel(const void* __restrict__ ei,
                                const float* __restrict__ xw,
                                const float* __restrict__ dinv,
                                float* __restrict__ agg) {
    int w = (blockIdx.x * blockDim.x + threadIdx.x) >> 5;
    if (w >= N_EDGES) return;
    const int lane = threadIdx.x & 31;
    int s, d;
    load_edge(ei, w, s, d);
    const float c = __ldg(&dinv[s]) * __ldg(&dinv[d]);
    const float4* xr = reinterpret_cast<const float4*>(xw) + (size_t)s * C4;
    float4*       ar = reinterpret_cast<float4*>(agg)      + (size_t)d * C4;
    #pragma unroll
    for (int j = lane; j < C4; j += 32) {
        float4 v = xr[j];
        v.x *= c; v.y *= c; v.z *= c; v.w *= c;
        atomicAdd(&ar[j], v);   // vector RED (sm_90+)
    }
}

// ---------------- self term + bias + ReLU (in place on agg) ----------------
template <int C>
__global__ void self_relu_kernel(float* __restrict__ agg,
                                 const float* __restrict__ xw,
                                 const float* __restrict__ dinv,
                                 const float* __restrict__ bias) {
    int idx = blockIdx.x * blockDim.x + threadIdx.x;   // over float4 units
    const int C4 = C / 4;
    if (idx >= N_NODES * C4) return;
    int row = idx / C4;
    int c4  = idx - row * C4;
    float di = dinv[row];
    float cc = di * di;
    float4 a = reinterpret_cast<float4*>(agg)[idx];
    float4 x = reinterpret_cast<const float4*>(xw)[idx];
    float4 b = reinterpret_cast<const float4*>(bias)[c4];
    a.x = fmaxf(fmaf(x.x, cc, a.x) + b.x, 0.f);
    a.y = fmaxf(fmaf(x.y, cc, a.y) + b.y, 0.f);
    a.z = fmaxf(fmaf(x.z, cc, a.z) + b.z, 0.f);
    a.w = fmaxf(fmaf(x.w, cc, a.w) + b.w, 0.f);
    reinterpret_cast<float4*>(agg)[idx] = a;
}

// ---------------- launch ----------------
extern "C" void kernel_launch(void* const* d_in, const int* in_sizes, int n_in,
                              void* d_out, int out_size) {
    const float* x    = (const float*)d_in[0];
    const void*  ei   = d_in[1];
    const float* W1   = (const float*)d_in[2];
    const float* b1   = (const float*)d_in[3];
    const float* W2   = (const float*)d_in[4];
    const float* b2   = (const float*)d_in[5];
    const float* fcW1 = (const float*)d_in[6];
    const float* fcb1 = (const float*)d_in[7];
    const float* fcW2 = (const float*)d_in[8];
    const float* fcb2 = (const float*)d_in[9];
    float* out = (float*)d_out;

    float *deg, *dinv, *xw1, *agg1, *xw2, *agg2;
    cudaGetSymbolAddress((void**)&deg,  g_deg);
    cudaGetSymbolAddress((void**)&dinv, g_dinv);
    cudaGetSymbolAddress((void**)&xw1,  g_xw1);
    cudaGetSymbolAddress((void**)&agg1, g_agg1);
    cudaGetSymbolAddress((void**)&xw2,  g_xw2);
    cudaGetSymbolAddress((void**)&agg2, g_agg2);

    // dtype probe + init + degrees
    detect_kernel<<<1, 32>>>(ei);
    init_kernel<<<(N_NODES * C1 / 4 + 255) / 256, 256>>>(deg, agg1, agg2);
    deg_kernel<<<(N_EDGES + 255) / 256, 256>>>(ei, deg);
    dinv_kernel<<<(N_NODES + 255) / 256, 256>>>(deg, dinv);

    const int edge_blocks = (N_EDGES * 32 + 255) / 256;   // one warp per edge

    // ---- layer 1: xw1 = x @ W1 ; aggregate ; h = relu(agg + self + b1) (in agg1)
    {
        dim3 grid(C1 / 128, (N_NODES + 127) / 128);
        sgemm_kernel<<<grid, 256>>>(x, W1, nullptr, xw1, N_NODES, C1, 128, 0);
    }
    edge_agg_kernel<C1 / 4><<<edge_blocks, 256>>>(ei, xw1, dinv, agg1);
    self_relu_kernel<C1><<<(N_NODES * C1 / 4 + 255) / 256, 256>>>(agg1, xw1, dinv, b1);

    // ---- layer 2: xw2 = h @ W2 ; aggregate ; z = relu(agg + self + b2) (in agg2)
    {
        dim3 grid(C2 / 128, (N_NODES + 127) / 128);
        sgemm_kernel<<<grid, 256>>>(agg1, W2, nullptr, xw2, N_NODES, C2, C1, 0);
    }
    edge_agg_kernel<C2 / 4><<<edge_blocks, 256>>>(ei, xw2, dinv, agg2);
    self_relu_kernel<C2><<<(N_NODES * C2 / 4 + 255) / 256, 256>>>(agg2, xw2, dinv, b2);

    // ---- projection head: p = elu(z @ fcW1 + fcb1) (into xw2) ; out = p @ fcW2 + fcb2
    {
        dim3 grid(C2 / 128, (N_NODES + 127) / 128);
        sgemm_kernel<<<grid, 256>>>(agg2, fcW1, fcb1, xw2, N_NODES, C2, C2, 2);
        sgemm_kernel<<<grid, 256>>>(xw2, fcW2, fcb2, out, N_NODES, C2, C2, 0);
    }
}

// round 4
// speedup vs baseline: 1.4336x; 1.4336x over previous
#include <cuda_runtime.h>
#include <math.h>

#define N_NODES 50000
#define N_EDGES 800000
#define C1 256
#define C2 128

// ---------------- scratch (allocation-free: __device__ globals) ----------------
__device__ int   g_is64;                  // 1 if edge_index is int64, 0 if int32
__device__ int   g_counts [N_NODES];      // in-degree (no self loop)
__device__ int   g_offsets[N_NODES];      // CSR row starts
__device__ int   g_cursor [N_NODES];      // scatter cursors
__device__ int   g_csr_src[N_EDGES];      // src node per CSR slot
__device__ float g_dinv   [N_NODES];
__device__ float g_aggx   [N_NODES * C2]; // aggregated x; later reused for p (25.6 MB)
__device__ float g_h      [N_NODES * C1]; // relu(aggx @ W1 + b1)            (51.2 MB)
__device__ float g_xw2    [N_NODES * C2]; // h @ W2                          (25.6 MB)
__device__ float g_z      [N_NODES * C2]; // layer-2 output                  (25.6 MB)

// ---------------- dtype probe: int64 vs int32 edge_index ----------------
__global__ void detect_kernel(const void* __restrict__ ei) {
    if (threadIdx.x == 0 && blockIdx.x == 0) {
        const long long* p = (const long long*)ei;
        int ok64 = 1;
        #pragma unroll
        for (int i = 0; i < 16; i++) {
            long long v = p[i];
            if (v < 0 || v >= N_NODES) ok64 = 0;
        }
        g_is64 = ok64;
    }
}

__device__ __forceinline__ void load_edge(const void* __restrict__ ei, int e,
                                          int& s, int& d) {
    if (g_is64) {
        const long long* p = (const long long*)ei;
        s = (int)p[e];
        d = (int)p[N_EDGES + e];
    } else {
        const int* p = (const int*)ei;
        s = p[e];
        d = p[N_EDGES + e];
    }
    if ((unsigned)s >= N_NODES) s = 0;   // defensive: never fault
    if ((unsigned)d >= N_NODES) d = 0;
}

// ---------------- CSR build ----------------
__global__ void zero_counts_kernel(int* __restrict__ counts) {
    int i = blockIdx.x * blockDim.x + threadIdx.x;
    if (i < N_NODES) counts[i] = 0;
}

__global__ void count_kernel(const void* __restrict__ ei, int* __restrict__ counts) {
    int e = blockIdx.x * blockDim.x + threadIdx.x;
    if (e < N_EDGES) {
        int s, d;
        load_edge(ei, e, s, d);
        atomicAdd(&counts[d], 1);
    }
}

// single-block exclusive scan over 50K ints; also emits dinv = rsqrt(deg+1)
__global__ __launch_bounds__(1024)
void scan_kernel(const int* __restrict__ counts, int* __restrict__ offsets,
                 int* __restrict__ cursor, float* __restrict__ dinv) {
    __shared__ int sh_carry;
    __shared__ int warp_tot[32];
    const int tid = threadIdx.x, lane = tid & 31, wid = tid >> 5;
    if (tid == 0) sh_carry = 0;
    __syncthreads();
    for (int base = 0; base < N_NODES; base += 1024) {
        int i = base + tid;
        int v = (i < N_NODES) ? counts[i] : 0;
        int x = v;
        #pragma unroll
        for (int o = 1; o < 32; o <<= 1) {
            int y = __shfl_up_sync(0xffffffffu, x, o);
            if (lane >= o) x += y;
        }
        if (lane == 31) warp_tot[wid] = x;
        __syncthreads();
        int carry = sh_carry;
        if (wid == 0) {
            int s = warp_tot[lane];
            #pragma unroll
            for (int o = 1; o < 32; o <<= 1) {
                int y = __shfl_up_sync(0xffffffffu, s, o);
                if (lane >= o) s += y;
            }
            warp_tot[lane] = s;
        }
        __syncthreads();
        int woff = wid ? warp_tot[wid - 1] : 0;
        int excl = carry + woff + (x - v);
        if (i < N_NODES) {
            offsets[i] = excl;
            cursor[i]  = excl;
            dinv[i]    = rsqrtf((float)v + 1.0f);
        }
        __syncthreads();
        if (tid == 0) sh_carry = carry + warp_tot[31];
        __syncthreads();
    }
}

__global__ void scatter_kernel(const void* __restrict__ ei, int* __restrict__ cursor,
                               int* __restrict__ csr_src) {
    int e = blockIdx.x * blockDim.x + threadIdx.x;
    if (e < N_EDGES) {
        int s, d;
        load_edge(ei, e, s, d);
        int pos = atomicAdd(&cursor[d], 1);
        csr_src[pos] = s;
    }
}

// ---------------- gather aggregation (warp per node, C=128) ----------------
// out[n] = sum_{src in N(n)} dinv[src]*dinv[n]*feat[src] + dinv[n]^2*feat[n]
// mode 1: + bias, relu. mode 0: raw.
__global__ __launch_bounds__(256)
void gather_kernel(const int* __restrict__ csr_src, const int* __restrict__ offsets,
                   const int* __restrict__ counts, const float* __restrict__ dinv,
                   const float* __restrict__ feat, const float* __restrict__ bias,
                   float* __restrict__ out, int mode) {
    int n = blockIdx.x * 8 + (threadIdx.x >> 5);
    if (n >= N_NODES) return;
    const int lane = threadIdx.x & 31;
    const int start = offsets[n];
    const int cnt   = counts[n];
    const float di  = dinv[n];
    const float4* base = (const float4*)feat;

    float4 acc;
    {
        float c = di * di;
        float4 v = base[(size_t)n * 32 + lane];
        acc = make_float4(v.x * c, v.y * c, v.z * c, v.w * c);
    }
    int s = (cnt > 0) ? __ldg(&csr_src[start]) : 0;
    for (int e = 0; e < cnt; e++) {
        int snext = (e + 1 < cnt) ? __ldg(&csr_src[start + e + 1]) : 0;
        float c = __ldg(&dinv[s]) * di;
        float4 v = __ldg(&base[(size_t)s * 32 + lane]);
        acc.x = fmaf(v.x, c, acc.x);
        acc.y = fmaf(v.y, c, acc.y);
        acc.z = fmaf(v.z, c, acc.z);
        acc.w = fmaf(v.w, c, acc.w);
        s = snext;
    }
    if (mode) {
        float4 b = ((const float4*)bias)[lane];
        acc.x = fmaxf(acc.x + b.x, 0.f);
        acc.y = fmaxf(acc.y + b.y, 0.f);
        acc.z = fmaxf(acc.z + b.z, 0.f);
        acc.w = fmaxf(acc.w + b.w, 0.f);
    }
    ((float4*)out)[(size_t)n * 32 + lane] = acc;
}

// ---------------- fp32 SGEMM, BK=16 double-buffered ----------------
// C = act(A[MxK] @ B[KxN] + bias). act: 0 none, 1 relu, 2 elu.
__global__ __launch_bounds__(256)
void sgemm_kernel(const float* __restrict__ A, const float* __restrict__ B,
                  const float* __restrict__ bias, float* __restrict__ C,
                  int M, int N, int K, int act) {
    __shared__ float As[2][16][128];
    __shared__ float Bs[2][16][128];

    const int bn = blockIdx.x * 128;
    const int bm = blockIdx.y * 128;
    const int tid = threadIdx.x;
    const int tx = tid & 15;
    const int ty = tid >> 4;

    // A: 128 rows x 16 k = 512 float4, 2 per thread (transposed into As)
    const int ar0 = tid >> 2,           ak0 = (tid & 3) * 4;
    const int ar1 = (tid + 256) >> 2,   ak1 = (tid & 3) * 4;   // (tid+256)&3 == tid&3
    const bool av0 = (bm + ar0) < M;
    const bool av1 = (bm + ar1) < M;
    const float* Ap0 = A + (size_t)(av0 ? bm + ar0 : 0) * K;
    const float* Ap1 = A + (size_t)(av1 ? bm + ar1 : 0) * K;
    // B: 16 rows x 128 cols = 512 float4, 2 per thread
    const int br0 = tid >> 5,         bc0 = (tid & 31) * 4;
    const int br1 = (tid + 256) >> 5, bc1 = (tid & 31) * 4;

    float acc[8][8];
    #pragma unroll
    for (int i = 0; i < 8; i++)
        #pragma unroll
        for (int j = 0; j < 8; j++) acc[i][j] = 0.f;

    const float4 z4 = make_float4(0.f, 0.f, 0.f, 0.f);

    // prologue: tile 0
    {
        float4 fa0 = av0 ? *(const float4*)(Ap0 + ak0) : z4;
        float4 fa1 = av1 ? *(const float4*)(Ap1 + ak1) : z4;
        float4 fb0 = *(const float4*)(B + (size_t)br0 * N + bn + bc0);
        float4 fb1 = *(const float4*)(B + (size_t)br1 * N + bn + bc1);
        As[0][ak0 + 0][ar0] = fa0.x; As[0][ak0 + 1][ar0] = fa0.y;
        As[0][ak0 + 2][ar0] = fa0.z; As[0][ak0 + 3][ar0] = fa0.w;
        As[0][ak1 + 0][ar1] = fa1.x; As[0][ak1 + 1][ar1] = fa1.y;
        As[0][ak1 + 2][ar1] = fa1.z; As[0][ak1 + 3][ar1] = fa1.w;
        *(float4*)&Bs[0][br0][bc0] = fb0;
        *(float4*)&Bs[0][br1][bc1] = fb1;
    }
    __syncthreads();

    int cur = 0;
    for (int k0 = 16; k0 < K; k0 += 16) {
        // prefetch next tile into registers
        float4 fa0 = av0 ? *(const float4*)(Ap0 + k0 + ak0) : z4;
        float4 fa1 = av1 ? *(const float4*)(Ap1 + k0 + ak1) : z4;
        float4 fb0 = *(const float4*)(B + (size_t)(k0 + br0) * N + bn + bc0);
        float4 fb1 = *(const float4*)(B + (size_t)(k0 + br1) * N + bn + bc1);

        // compute on current buffer
        #pragma unroll
        for (int kk = 0; kk < 16; kk++) {
            float4 a0 = *(const float4*)&As[cur][kk][ty * 8];
            float4 a1 = *(const float4*)&As[cur][kk][ty * 8 + 4];
            float4 b0 = *(const float4*)&Bs[cur][kk][tx * 8];
            float4 b1 = *(const float4*)&Bs[cur][kk][tx * 8 + 4];
            float ar[8] = {a0.x, a0.y, a0.z, a0.w, a1.x, a1.y, a1.z, a1.w};
            float br[8] = {b0.x, b0.y, b0.z, b0.w, b1.x, b1.y, b1.z, b1.w};
            #pragma unroll
            for (int i = 0; i < 8; i++)
                #pragma unroll
                for (int j = 0; j < 8; j++)
                    acc[i][j] = fmaf(ar[i], br[j], acc[i][j]);
        }
        __syncthreads();
        int nxt = cur ^ 1;
        As[nxt][ak0 + 0][ar0] = fa0.x; As[nxt][ak0 + 1][ar0] = fa0.y;
        As[nxt][ak0 + 2][ar0] = fa0.z; As[nxt][ak0 + 3][ar0] = fa0.w;
        As[nxt][ak1 + 0][ar1] = fa1.x; As[nxt][ak1 + 1][ar1] = fa1.y;
        As[nxt][ak1 + 2][ar1] = fa1.z; As[nxt][ak1 + 3][ar1] = fa1.w;
        *(float4*)&Bs[nxt][br0][bc0] = fb0;
        *(float4*)&Bs[nxt][br1][bc1] = fb1;
        __syncthreads();
        cur = nxt;
    }
    // last tile
    #pragma unroll
    for (int kk = 0; kk < 16; kk++) {
        float4 a0 = *(const float4*)&As[cur][kk][ty * 8];
        float4 a1 = *(const float4*)&As[cur][kk][ty * 8 + 4];
        float4 b0 = *(const float4*)&Bs[cur][kk][tx * 8];
        float4 b1 = *(const float4*)&Bs[cur][kk][tx * 8 + 4];
        float ar[8] = {a0.x, a0.y, a0.z, a0.w, a1.x, a1.y, a1.z, a1.w};
        float br[8] = {b0.x, b0.y, b0.z, b0.w, b1.x, b1.y, b1.z, b1.w};
        #pragma unroll
        for (int i = 0; i < 8; i++)
            #pragma unroll
            for (int j = 0; j < 8; j++)
                acc[i][j] = fmaf(ar[i], br[j], acc[i][j]);
    }

    // epilogue
    #pragma unroll
    for (int i = 0; i < 8; i++) {
        int row = bm + ty * 8 + i;
        if (row >= M) break;
        float* Crow = C + (size_t)row * N + bn + tx * 8;
        #pragma unroll
        for (int j = 0; j < 8; j++) {
            float v = acc[i][j];
            if (bias) v += bias[bn + tx * 8 + j];
            if (act == 1) v = fmaxf(v, 0.f);
            if (act == 2) v = v > 0.f ? v : expm1f(v);   // ELU(alpha=1)
            Crow[j] = v;
        }
    }
}

// ---------------- launch ----------------
extern "C" void kernel_launch(void* const* d_in, const int* in_sizes, int n_in,
                              void* d_out, int out_size) {
    const float* x    = (const float*)d_in[0];
    const void*  ei   = d_in[1];
    const float* W1   = (const float*)d_in[2];
    const float* b1   = (const float*)d_in[3];
    const float* W2   = (const float*)d_in[4];
    const float* b2   = (const float*)d_in[5];
    const float* fcW1 = (const float*)d_in[6];
    const float* fcb1 = (const float*)d_in[7];
    const float* fcW2 = (const float*)d_in[8];
    const float* fcb2 = (const float*)d_in[9];
    float* out = (float*)d_out;

    int *counts, *offsets, *cursor, *csr_src;
    float *dinv, *aggx, *h, *xw2, *z;
    cudaGetSymbolAddress((void**)&counts,  g_counts);
    cudaGetSymbolAddress((void**)&offsets, g_offsets);
    cudaGetSymbolAddress((void**)&cursor,  g_cursor);
    cudaGetSymbolAddress((void**)&csr_src, g_csr_src);
    cudaGetSymbolAddress((void**)&dinv,    g_dinv);
    cudaGetSymbolAddress((void**)&aggx,    g_aggx);
    cudaGetSymbolAddress((void**)&h,       g_h);
    cudaGetSymbolAddress((void**)&xw2,     g_xw2);
    cudaGetSymbolAddress((void**)&z,       g_z);

    const int EB = (N_EDGES + 255) / 256;
    const int NB = (N_NODES + 255) / 256;
    const int GB = (N_NODES + 7) / 8;     // gather: warp per node, 8 warps/block

    // CSR build + dinv
    detect_kernel<<<1, 32>>>(ei);
    zero_counts_kernel<<<NB, 256>>>(counts);
    count_kernel<<<EB, 256>>>(ei, counts);
    scan_kernel<<<1, 1024>>>(counts, offsets, cursor, dinv);
    scatter_kernel<<<EB, 256>>>(ei, cursor, csr_src);

    // layer 1 (reordered): aggx = A_hat @ x ; h = relu(aggx @ W1 + b1)
    gather_kernel<<<GB, 256>>>(csr_src, offsets, counts, dinv, x, nullptr, aggx, 0);
    {
        dim3 grid(C1 / 128, (N_NODES + 127) / 128);
        sgemm_kernel<<<grid, 256>>>(aggx, W1, b1, h, N_NODES, C1, C2, 1);
    }

    // layer 2: xw2 = h @ W2 ; z = relu(A_hat @ xw2 + b2)
    {
        dim3 grid(C2 / 128, (N_NODES + 127) / 128);
        sgemm_kernel<<<grid, 256>>>(h, W2, nullptr, xw2, N_NODES, C2, C1, 0);
    }
    gather_kernel<<<GB, 256>>>(csr_src, offsets, counts, dinv, xw2, b2, z, 1);

    // projection head: p = elu(z @ fcW1 + fcb1) (into aggx) ; out = p @ fcW2 + fcb2
    {
        dim3 grid(C2 / 128, (N_NODES + 127) / 128);
        sgemm_kernel<<<grid, 256>>>(z, fcW1, fcb1, aggx, N_NODES, C2, C2, 2);
        sgemm_kernel<<<grid, 256>>>(aggx, fcW2, fcb2, out, N_NODES, C2, C2, 0);
    }
}

// round 6
// speedup vs baseline: 2.7506x; 1.9187x over previous
#include <cuda_runtime.h>
#include <cuda_bf16.h>
#include <math.h>
#include <stdint.h>

#define N_NODES 50000
#define N_EDGES 800000
#define C1 256
#define C2 128
#define SCAN_BLOCKS ((N_NODES + 255) / 256)   // 196

// ---------------- scratch (allocation-free: __device__ globals) ----------------
__device__ int   g_is64;
__device__ int   g_counts [N_NODES];
__device__ int   g_offsets[N_NODES];
__device__ int   g_cursor [N_NODES];
__device__ int   g_bsum   [SCAN_BLOCKS];
__device__ int   g_csr_src[N_EDGES];
__device__ float g_dinv   [N_NODES];
__device__ float g_xw2    [N_NODES * C2];       // GEMM2 fp32 output (feeds gather2)
__device__ __nv_bfloat16 g_p1h[N_NODES * C1];   // split pair 1 (aggx, later z)
__device__ __nv_bfloat16 g_p1l[N_NODES * C1];
__device__ __nv_bfloat16 g_p2h[N_NODES * C1];   // split pair 2 (h, later p)
__device__ __nv_bfloat16 g_p2l[N_NODES * C1];
__device__ __nv_bfloat16 g_Bh[256 * 256];       // transposed weight hi [N][K]
__device__ __nv_bfloat16 g_Bl[256 * 256];       // transposed weight lo

// ==================== PTX helpers (portable: sm_80+) ====================
__device__ __forceinline__ uint32_t smem_u32(const void* p) {
    uint32_t a;
    asm("{ .reg .u64 t; cvta.to.shared.u64 t, %1; cvt.u32.u64 %0, t; }" : "=r"(a) : "l"(p));
    return a;
}
__device__ __forceinline__ void ldsm_x4(uint32_t* r, uint32_t addr) {
    asm volatile("ldmatrix.sync.aligned.m8n8.x4.shared.b16 {%0,%1,%2,%3}, [%4];"
                 : "=r"(r[0]), "=r"(r[1]), "=r"(r[2]), "=r"(r[3]) : "r"(addr));
}
__device__ __forceinline__ void mma16816(float* d, const uint32_t* a, const uint32_t* b) {
    asm volatile(
        "mma.sync.aligned.m16n8k16.row.col.f32.bf16.bf16.f32 "
        "{%0,%1,%2,%3}, {%4,%5,%6,%7}, {%8,%9}, {%0,%1,%2,%3};"
        : "+f"(d[0]), "+f"(d[1]), "+f"(d[2]), "+f"(d[3])
        : "r"(a[0]), "r"(a[1]), "r"(a[2]), "r"(a[3]), "r"(b[0]), "r"(b[1]));
}
__device__ __forceinline__ void cp_async16(uint32_t dst, const void* src, int src_bytes) {
    asm volatile("cp.async.cg.shared.global [%0], [%1], 16, %2;"
                 :: "r"(dst), "l"(src), "r"(src_bytes) : "memory");
}
#define CP_COMMIT() asm volatile("cp.async.commit_group;" ::: "memory")
template <int W>
__device__ __forceinline__ void cp_wait() {
    asm volatile("cp.async.wait_group %0;" :: "n"(W) : "memory");
}
__device__ __forceinline__ uint32_t pack_bf16x2(__nv_bfloat16 lo, __nv_bfloat16 hi) {
    return ((uint32_t)__bfloat16_as_ushort(hi) << 16) | __bfloat16_as_ushort(lo);
}
__device__ __forceinline__ void split_bf16(float v, __nv_bfloat16& h, __nv_bfloat16& l) {
    h = __float2bfloat16(v);
    l = __float2bfloat16(v - __bfloat162float(h));
}

// ==================== edge-index handling ====================
__global__ void detect_kernel(const void* __restrict__ ei) {
    if (threadIdx.x == 0 && blockIdx.x == 0) {
        const long long* p = (const long long*)ei;
        int ok64 = 1;
        #pragma unroll
        for (int i = 0; i < 16; i++) {
            long long v = p[i];
            if (v < 0 || v >= N_NODES) ok64 = 0;
        }
        g_is64 = ok64;
    }
}
__device__ __forceinline__ void load_edge(const void* __restrict__ ei, int e, int& s, int& d) {
    if (g_is64) {
        const long long* p = (const long long*)ei;
        s = (int)p[e]; d = (int)p[N_EDGES + e];
    } else {
        const int* p = (const int*)ei;
        s = p[e]; d = p[N_EDGES + e];
    }
    if ((unsigned)s >= N_NODES) s = 0;
    if ((unsigned)d >= N_NODES) d = 0;
}

// ==================== CSR build ====================
__global__ void zero_counts_kernel(int* __restrict__ counts) {
    int i = blockIdx.x * blockDim.x + threadIdx.x;
    if (i < N_NODES) counts[i] = 0;
}
__global__ void count_kernel(const void* __restrict__ ei, int* __restrict__ counts) {
    int e = blockIdx.x * blockDim.x + threadIdx.x;
    if (e < N_EDGES) {
        int s, d; load_edge(ei, e, s, d);
        atomicAdd(&counts[d], 1);
    }
}
__global__ void scanA_kernel(const int* __restrict__ counts, int* __restrict__ offsets,
                             int* __restrict__ bsum) {
    __shared__ int wt[8];
    int tid = threadIdx.x, lane = tid & 31, wid = tid >> 5;
    int i = blockIdx.x * 256 + tid;
    int v = (i < N_NODES) ? counts[i] : 0;
    int x = v;
    #pragma unroll
    for (int o = 1; o < 32; o <<= 1) { int y = __shfl_up_sync(0xffffffffu, x, o); if (lane >= o) x += y; }
    if (lane == 31) wt[wid] = x;
    __syncthreads();
    if (wid == 0) {
        int s = (lane < 8) ? wt[lane] : 0;
        #pragma unroll
        for (int o = 1; o < 8; o <<= 1) { int y = __shfl_up_sync(0xffffffffu, s, o); if (lane >= o) s += y; }
        if (lane < 8) wt[lane] = s;
    }
    __syncthreads();
    int base = wid ? wt[wid - 1] : 0;
    if (i < N_NODES) offsets[i] = base + x - v;
    if (tid == 255) bsum[blockIdx.x] = base + x;
}
__global__ void scanB_kernel(int* __restrict__ bsum) {
    __shared__ int wt[8];
    int tid = threadIdx.x, lane = tid & 31, wid = tid >> 5;
    int v = (tid < SCAN_BLOCKS) ? bsum[tid] : 0;
    int x = v;
    #pragma unroll
    for (int o = 1; o < 32; o <<= 1) { int y = __shfl_up_sync(0xffffffffu, x, o); if (lane >= o) x += y; }
    if (lane == 31) wt[wid] = x;
    __syncthreads();
    if (wid == 0) {
        int s = (lane < 8) ? wt[lane] : 0;
        #pragma unroll
        for (int o = 1; o < 8; o <<= 1) { int y = __shfl_up_sync(0xffffffffu, s, o); if (lane >= o) s += y; }
        if (lane < 8) wt[lane] = s;
    }
    __syncthreads();
    int base = wid ? wt[wid - 1] : 0;
    if (tid < SCAN_BLOCKS) bsum[tid] = base + x - v;
}
__global__ void scanC_kernel(int* __restrict__ offsets, const int* __restrict__ bsum,
                             const int* __restrict__ counts, int* __restrict__ cursor,
                             float* __restrict__ dinv) {
    int i = blockIdx.x * 256 + threadIdx.x;
    if (i < N_NODES) {
        int off = offsets[i] + bsum[blockIdx.x];
        offsets[i] = off;
        cursor[i]  = off;
        dinv[i]    = rsqrtf((float)counts[i] + 1.0f);
    }
}
__global__ void scatter_kernel(const void* __restrict__ ei, int* __restrict__ cursor,
                               int* __restrict__ csr_src) {
    int e = blockIdx.x * blockDim.x + threadIdx.x;
    if (e < N_EDGES) {
        int s, d; load_edge(ei, e, s, d);
        int pos = atomicAdd(&cursor[d], 1);
        csr_src[pos] = s;
    }
}

// ==================== gather aggregation (warp per node, C=128) -> bf16 split ====
// out = sum_{src} dinv[s]*dinv[n]*feat[s] + dinv[n]^2*feat[n]  (+bias, relu if mode)
__global__ __launch_bounds__(256)
void gather_kernel(const int* __restrict__ csr_src, const int* __restrict__ offsets,
                   const int* __restrict__ counts, const float* __restrict__ dinv,
                   const float* __restrict__ feat, const float* __restrict__ bias,
                   __nv_bfloat16* __restrict__ outh, __nv_bfloat16* __restrict__ outl,
                   int mode) {
    int n = blockIdx.x * 8 + (threadIdx.x >> 5);
    if (n >= N_NODES) return;
    const int lane = threadIdx.x & 31;
    const int start = offsets[n];
    const int cnt   = counts[n];
    const float di  = dinv[n];
    const float4* base = (const float4*)feat;
    float4 acc;
    {
        float c = di * di;
        float4 v = base[(size_t)n * 32 + lane];
        acc = make_float4(v.x * c, v.y * c, v.z * c, v.w * c);
    }
    int s = (cnt > 0) ? __ldg(&csr_src[start]) : 0;
    for (int e = 0; e < cnt; e++) {
        int snext = (e + 1 < cnt) ? __ldg(&csr_src[start + e + 1]) : 0;
        float c = __ldg(&dinv[s]) * di;
        float4 v = __ldg(&base[(size_t)s * 32 + lane]);
        acc.x = fmaf(v.x, c, acc.x);
        acc.y = fmaf(v.y, c, acc.y);
        acc.z = fmaf(v.z, c, acc.z);
        acc.w = fmaf(v.w, c, acc.w);
        s = snext;
    }
    if (mode) {
        float4 b = ((const float4*)bias)[lane];
        acc.x = fmaxf(acc.x + b.x, 0.f);
        acc.y = fmaxf(acc.y + b.y, 0.f);
        acc.z = fmaxf(acc.z + b.z, 0.f);
        acc.w = fmaxf(acc.w + b.w, 0.f);
    }
    __nv_bfloat16 h0, h1, h2, h3, l0, l1, l2, l3;
    split_bf16(acc.x, h0, l0); split_bf16(acc.y, h1, l1);
    split_bf16(acc.z, h2, l2); split_bf16(acc.w, h3, l3);
    uint32_t* oh = (uint32_t*)(outh + (size_t)n * 128 + lane * 4);
    uint32_t* ol = (uint32_t*)(outl + (size_t)n * 128 + lane * 4);
    oh[0] = pack_bf16x2(h0, h1); oh[1] = pack_bf16x2(h2, h3);
    ol[0] = pack_bf16x2(l0, l1); ol[1] = pack_bf16x2(l2, l3);
}

// ==================== weight transpose + bf16 split:  W[K,N] -> Bh/Bl[N,K] ====================
__global__ void wconv_kernel(const float* __restrict__ W, __nv_bfloat16* __restrict__ Bh,
                             __nv_bfloat16* __restrict__ Bl, int K, int N) {
    int idx = blockIdx.x * blockDim.x + threadIdx.x;
    if (idx < K * N) {
        int n = idx / K, k = idx - n * K;
        float w = W[(size_t)k * N + n];
        __nv_bfloat16 h, l;
        split_bf16(w, h, l);
        Bh[idx] = h;
        Bl[idx] = l;
    }
}

// ==================== bf16-split GEMM via mma.sync (HMMA) ====================
// C[M,N] = act(A @ W + bias); A given as bf16 hi/lo [M,K]; W as Bh/Bl [N,K].
// acc = AhBh + AlBh + AhBl (fp32 accumulators).
// ACT: 0 none(no bias), 1 bias+relu, 2 bias+elu, 3 bias only.
// SPLIT_OUT: write bf16 hi/lo pair instead of fp32.
#define PADK 40   // 32 + 8 bf16 pad: 80B row stride, conflict-free ldmatrix
template <int ACT, bool SPLIT_OUT>
__global__ void __launch_bounds__(256)
mma_gemm_kernel(const __nv_bfloat16* __restrict__ Ah, const __nv_bfloat16* __restrict__ Al,
                const __nv_bfloat16* __restrict__ Bh, const __nv_bfloat16* __restrict__ Bl,
                const float* __restrict__ bias,
                float* __restrict__ C, __nv_bfloat16* __restrict__ Ch,
                __nv_bfloat16* __restrict__ Cl, int M, int N, int K) {
    extern __shared__ char smem[];
    // regions: [2 bufs][128][PADK] bf16 each = 20480 B per operand
    const uint32_t uAh = smem_u32(smem);
    const uint32_t uAl = uAh + 20480;
    const uint32_t uBh = uAl + 20480;
    const uint32_t uBl = uBh + 20480;

    const int tid  = threadIdx.x;
    const int lane = tid & 31;
    const int wid  = tid >> 5;
    const int wm   = wid & 3;          // 4 warps along M -> 32 rows each
    const int wn   = wid >> 2;         // 2 warps along N -> 64 cols each
    const int bn   = blockIdx.x * 128;
    const int bm   = blockIdx.y * 128;
    const int S    = K >> 5;           // BK=32 stages

    float acc[2][8][4];
    #pragma unroll
    for (int i = 0; i < 2; i++)
        #pragma unroll
        for (int j = 0; j < 8; j++)
            #pragma unroll
            for (int q = 0; q < 4; q++) acc[i][j][q] = 0.f;

    // tile loader: 128 rows x 32 bf16 = 512 x 16B chunks; 2 chunks/thread/operand
    const int c0   = tid * 2;
    const int row0 = c0 >> 2,  kc0v = (c0 & 3) * 8;
    const int row1 = row0,     kc1v = kc0v + 8;   // c0+1: same row (c0 even), next 16B
    auto load_stage = [&](int s) {
        const int k0 = s * 32;
        const int buf = (s & 1) * 10240;
        const bool v0 = (bm + row0) < M;
        size_t aoff0 = (size_t)(v0 ? bm + row0 : 0) * K + k0;
        cp_async16(uAh + buf + (row0 * PADK + kc0v) * 2, Ah + aoff0 + kc0v, v0 ? 16 : 0);
        cp_async16(uAh + buf + (row1 * PADK + kc1v) * 2, Ah + aoff0 + kc1v, v0 ? 16 : 0);
        cp_async16(uAl + buf + (row0 * PADK + kc0v) * 2, Al + aoff0 + kc0v, v0 ? 16 : 0);
        cp_async16(uAl + buf + (row1 * PADK + kc1v) * 2, Al + aoff0 + kc1v, v0 ? 16 : 0);
        size_t boff0 = (size_t)(bn + row0) * K + k0;
        cp_async16(uBh + buf + (row0 * PADK + kc0v) * 2, Bh + boff0 + kc0v, 16);
        cp_async16(uBh + buf + (row1 * PADK + kc1v) * 2, Bh + boff0 + kc1v, 16);
        cp_async16(uBl + buf + (row0 * PADK + kc0v) * 2, Bl + boff0 + kc0v, 16);
        cp_async16(uBl + buf + (row1 * PADK + kc1v) * 2, Bl + boff0 + kc1v, 16);
    };

    // frag address offsets (within a buffer)
    const int a_r = wm * 32 + (lane & 15);
    const int a_c = (lane >> 4) * 8;
    const int bj  = lane >> 3;
    const int b_r = wn * 64 + ((bj >> 1) << 3) + (lane & 7);
    const int b_c = (bj & 1) << 3;

    load_stage(0);
    CP_COMMIT();
    for (int s = 0; s < S; s++) {
        if (s + 1 < S) { load_stage(s + 1); CP_COMMIT(); cp_wait<1>(); }
        else cp_wait<0>();
        __syncthreads();
        const int buf = (s & 1) * 10240;
        #pragma unroll
        for (int k16 = 0; k16 < 32; k16 += 16) {
            uint32_t aH[2][4], aL[2][4], bH[8][2];
            #pragma unroll
            for (int f = 0; f < 2; f++) {
                ldsm_x4(aH[f], uAh + buf + ((a_r + f * 16) * PADK + k16 + a_c) * 2);
                ldsm_x4(aL[f], uAl + buf + ((a_r + f * 16) * PADK + k16 + a_c) * 2);
            }
            #pragma unroll
            for (int nf = 0; nf < 4; nf++) {
                uint32_t r[4];
                ldsm_x4(r, uBh + buf + ((b_r + nf * 16) * PADK + k16 + b_c) * 2);
                bH[nf * 2][0] = r[0]; bH[nf * 2][1] = r[1];
                bH[nf * 2 + 1][0] = r[2]; bH[nf * 2 + 1][1] = r[3];
            }
            #pragma unroll
            for (int mi = 0; mi < 2; mi++)
                #pragma unroll
                for (int ni = 0; ni < 8; ni++) {
                    mma16816(acc[mi][ni], aH[mi], bH[ni]);
                    mma16816(acc[mi][ni], aL[mi], bH[ni]);
                }
            // third term: Ah * Bl (reuse bH regs)
            #pragma unroll
            for (int nf = 0; nf < 4; nf++) {
                uint32_t r[4];
                ldsm_x4(r, uBl + buf + ((b_r + nf * 16) * PADK + k16 + b_c) * 2);
                bH[nf * 2][0] = r[0]; bH[nf * 2][1] = r[1];
                bH[nf * 2 + 1][0] = r[2]; bH[nf * 2 + 1][1] = r[3];
            }
            #pragma unroll
            for (int mi = 0; mi < 2; mi++)
                #pragma unroll
                for (int ni = 0; ni < 8; ni++)
                    mma16816(acc[mi][ni], aH[mi], bH[ni]);
        }
        __syncthreads();
    }

    // ---- epilogue
    const int g = lane >> 2, tig = lane & 3;
    float bb[8][2];
    if (ACT != 0) {
        #pragma unroll
        for (int ni = 0; ni < 8; ni++) {
            int col = bn + wn * 64 + ni * 8 + tig * 2;
            bb[ni][0] = bias[col];
            bb[ni][1] = bias[col + 1];
        }
    }
    #pragma unroll
    for (int mi = 0; mi < 2; mi++) {
        int r0 = bm + wm * 32 + mi * 16 + g;
        #pragma unroll
        for (int half = 0; half < 2; half++) {
            int row = r0 + half * 8;
            if (row >= M) continue;
            #pragma unroll
            for (int ni = 0; ni < 8; ni++) {
                int col = bn + wn * 64 + ni * 8 + tig * 2;
                float v0 = acc[mi][ni][half * 2 + 0];
                float v1 = acc[mi][ni][half * 2 + 1];
                if (ACT != 0) { v0 += bb[ni][0]; v1 += bb[ni][1]; }
                if (ACT == 1) { v0 = fmaxf(v0, 0.f); v1 = fmaxf(v1, 0.f); }
                if (ACT == 2) {
                    v0 = v0 > 0.f ? v0 : expm1f(v0);
                    v1 = v1 > 0.f ? v1 : expm1f(v1);
                }
                if (SPLIT_OUT) {
                    __nv_bfloat16 h0, l0, h1, l1;
                    split_bf16(v0, h0, l0); split_bf16(v1, h1, l1);
                    *(uint32_t*)(Ch + (size_t)row * N + col) = pack_bf16x2(h0, h1);
                    *(uint32_t*)(Cl + (size_t)row * N + col) = pack_bf16x2(l0, l1);
                } else {
                    *(float2*)(C + (size_t)row * N + col) = make_float2(v0, v1);
                }
            }
        }
    }
}

// ==================== launch ====================
extern "C" void kernel_launch(void* const* d_in, const int* in_sizes, int n_in,
                              void* d_out, int out_size) {
    const float* x    = (const float*)d_in[0];
    const void*  ei   = d_in[1];
    const float* W1   = (const float*)d_in[2];
    const float* b1   = (const float*)d_in[3];
    const float* W2   = (const float*)d_in[4];
    const float* b2   = (const float*)d_in[5];
    const float* fcW1 = (const float*)d_in[6];
    const float* fcb1 = (const float*)d_in[7];
    const float* fcW2 = (const float*)d_in[8];
    const float* fcb2 = (const float*)d_in[9];
    float* out = (float*)d_out;

    int *counts, *offsets, *cursor, *csr_src, *bsum;
    float *dinv, *xw2;
    __nv_bfloat16 *p1h, *p1l, *p2h, *p2l, *Bh, *Bl;
    cudaGetSymbolAddress((void**)&counts,  g_counts);
    cudaGetSymbolAddress((void**)&offsets, g_offsets);
    cudaGetSymbolAddress((void**)&cursor,  g_cursor);
    cudaGetSymbolAddress((void**)&csr_src, g_csr_src);
    cudaGetSymbolAddress((void**)&bsum,    g_bsum);
    cudaGetSymbolAddress((void**)&dinv,    g_dinv);
    cudaGetSymbolAddress((void**)&xw2,     g_xw2);
    cudaGetSymbolAddress((void**)&p1h,     g_p1h);
    cudaGetSymbolAddress((void**)&p1l,     g_p1l);
    cudaGetSymbolAddress((void**)&p2h,     g_p2h);
    cudaGetSymbolAddress((void**)&p2l,     g_p2l);
    cudaGetSymbolAddress((void**)&Bh,      g_Bh);
    cudaGetSymbolAddress((void**)&Bl,      g_Bl);

    const int EB = (N_EDGES + 255) / 256;
    const int GB = (N_NODES + 7) / 8;
    const int MBY = (N_NODES + 127) / 128;    // 391
    constexpr int GSMEM = 4 * 20480;          // 81920 B dynamic

    cudaFuncSetAttribute(mma_gemm_kernel<1, true>,  cudaFuncAttributeMaxDynamicSharedMemorySize, GSMEM);
    cudaFuncSetAttribute(mma_gemm_kernel<0, false>, cudaFuncAttributeMaxDynamicSharedMemorySize, GSMEM);
    cudaFuncSetAttribute(mma_gemm_kernel<2, true>,  cudaFuncAttributeMaxDynamicSharedMemorySize, GSMEM);
    cudaFuncSetAttribute(mma_gemm_kernel<3, false>, cudaFuncAttributeMaxDynamicSharedMemorySize, GSMEM);

    // ---- CSR build + dinv (parallel scan)
    detect_kernel<<<1, 32>>>(ei);
    zero_counts_kernel<<<SCAN_BLOCKS, 256>>>(counts);
    count_kernel<<<EB, 256>>>(ei, counts);
    scanA_kernel<<<SCAN_BLOCKS, 256>>>(counts, offsets, bsum);
    scanB_kernel<<<1, 256>>>(bsum);
    scanC_kernel<<<SCAN_BLOCKS, 256>>>(offsets, bsum, counts, cursor, dinv);
    scatter_kernel<<<EB, 256>>>(ei, cursor, csr_src);

    // ---- layer 1: aggx = A_hat @ x (split) ; h = relu(aggx @ W1 + b1) (split)
    gather_kernel<<<GB, 256>>>(csr_src, offsets, counts, dinv, x, nullptr, p1h, p1l, 0);
    wconv_kernel<<<(128 * 256 + 255) / 256, 256>>>(W1, Bh, Bl, 128, 256);
    {
        dim3 grid(C1 / 128, MBY);
        mma_gemm_kernel<1, true><<<grid, 256, GSMEM>>>(p1h, p1l, Bh, Bl, b1,
                                                       nullptr, p2h, p2l, N_NODES, C1, C2);
    }

    // ---- layer 2: xw2 = h @ W2 (fp32) ; z = relu(A_hat @ xw2 + b2) (split)
    wconv_kernel<<<(256 * 128 + 255) / 256, 256>>>(W2, Bh, Bl, 256, 128);
    {
        dim3 grid(C2 / 128, MBY);
        mma_gemm_kernel<0, false><<<grid, 256, GSMEM>>>(p2h, p2l, Bh, Bl, nullptr,
                                                        xw2, nullptr, nullptr, N_NODES, C2, C1);
    }
    gather_kernel<<<GB, 256>>>(csr_src, offsets, counts, dinv, xw2, b2, p1h, p1l, 1);

    // ---- projection head: p = elu(z @ fcW1 + fcb1) (split) ; out = p @ fcW2 + fcb2
    wconv_kernel<<<(128 * 128 + 255) / 256, 256>>>(fcW1, Bh, Bl, 128, 128);
    {
        dim3 grid(C2 / 128, MBY);
        mma_gemm_kernel<2, true><<<grid, 256, GSMEM>>>(p1h, p1l, Bh, Bl, fcb1,
                                                       nullptr, p2h, p2l, N_NODES, C2, C2);
    }
    wconv_kernel<<<(128 * 128 + 255) / 256, 256>>>(fcW2, Bh, Bl, 128, 128);
    {
        dim3 grid(C2 / 128, MBY);
        mma_gemm_kernel<3, false><<<grid, 256, GSMEM>>>(p2h, p2l, Bh, Bl, fcb2,
                                                        out, nullptr, nullptr, N_NODES, C2, C2);
    }
}

// round 7
// speedup vs baseline: 2.9542x; 1.0740x over previous
#include <cuda_runtime.h>
#include <cuda_bf16.h>
#include <math.h>
#include <stdint.h>

#define N_NODES 50000
#define N_EDGES 800000
#define C1 256
#define C2 128
#define SCAN_BLOCKS ((N_NODES + 255) / 256)   // 196

// ---------------- scratch (allocation-free: __device__ globals) ----------------
__device__ int   g_counts [N_NODES];
__device__ int   g_offsets[N_NODES];
__device__ int   g_cursor [N_NODES];
__device__ int   g_bsum   [SCAN_BLOCKS];
__device__ int   g_csr_src[N_EDGES];
__device__ float g_dinv   [N_NODES];
__device__ float g_xw2    [N_NODES * C2];       // GEMM2 fp32 output (feeds gather2)
__device__ __nv_bfloat16 g_p1h[N_NODES * C1];   // split pair 1 (aggx, later z)
__device__ __nv_bfloat16 g_p1l[N_NODES * C1];
__device__ __nv_bfloat16 g_p2h[N_NODES * C1];   // split pair 2 (h)
__device__ __nv_bfloat16 g_p2l[N_NODES * C1];
// dedicated weight buffers (B layout [N][K] row-major, bf16 hi/lo)
__device__ __nv_bfloat16 g_B1h[128 * 256], g_B1l[128 * 256];   // W1^T  [256][128]
__device__ __nv_bfloat16 g_B2h[256 * 128], g_B2l[256 * 128];   // W2^T  [128][256]
__device__ __nv_bfloat16 g_B3h[128 * 128], g_B3l[128 * 128];   // fcW1^T
__device__ __nv_bfloat16 g_B4h[128 * 128], g_B4l[128 * 128];   // fcW2^T

// ==================== PTX helpers (portable: sm_80+) ====================
__device__ __forceinline__ uint32_t smem_u32(const void* p) {
    uint32_t a;
    asm("{ .reg .u64 t; cvta.to.shared.u64 t, %1; cvt.u32.u64 %0, t; }" : "=r"(a) : "l"(p));
    return a;
}
__device__ __forceinline__ void ldsm_x4(uint32_t* r, uint32_t addr) {
    asm volatile("ldmatrix.sync.aligned.m8n8.x4.shared.b16 {%0,%1,%2,%3}, [%4];"
                 : "=r"(r[0]), "=r"(r[1]), "=r"(r[2]), "=r"(r[3]) : "r"(addr));
}
__device__ __forceinline__ void mma16816(float* d, const uint32_t* a, const uint32_t* b) {
    asm volatile(
        "mma.sync.aligned.m16n8k16.row.col.f32.bf16.bf16.f32 "
        "{%0,%1,%2,%3}, {%4,%5,%6,%7}, {%8,%9}, {%0,%1,%2,%3};"
        : "+f"(d[0]), "+f"(d[1]), "+f"(d[2]), "+f"(d[3])
        : "r"(a[0]), "r"(a[1]), "r"(a[2]), "r"(a[3]), "r"(b[0]), "r"(b[1]));
}
__device__ __forceinline__ void cp_async16(uint32_t dst, const void* src, int src_bytes) {
    asm volatile("cp.async.cg.shared.global [%0], [%1], 16, %2;"
                 :: "r"(dst), "l"(src), "r"(src_bytes) : "memory");
}
#define CP_COMMIT() asm volatile("cp.async.commit_group;" ::: "memory")
template <int W>
__device__ __forceinline__ void cp_wait() {
    asm volatile("cp.async.wait_group %0;" :: "n"(W) : "memory");
}
__device__ __forceinline__ uint32_t pack_bf16x2(__nv_bfloat16 lo, __nv_bfloat16 hi) {
    return ((uint32_t)__bfloat16_as_ushort(hi) << 16) | __bfloat16_as_ushort(lo);
}
__device__ __forceinline__ void split_bf16(float v, __nv_bfloat16& h, __nv_bfloat16& l) {
    h = __float2bfloat16(v);
    l = __float2bfloat16(v - __bfloat162float(h));
}

// ==================== edge-index handling (int64 vs int32, probed per block) ====
__device__ __forceinline__ int probe64(const void* __restrict__ ei) {
    const long long* p = (const long long*)ei;
    int ok = 1;
    #pragma unroll
    for (int i = 0; i < 16; i++) {
        long long v = p[i];
        if (v < 0 || v >= N_NODES) ok = 0;
    }
    return ok;
}
__device__ __forceinline__ void load_edge(const void* __restrict__ ei, int is64, int e,
                                          int& s, int& d) {
    if (is64) {
        const long long* p = (const long long*)ei;
        s = (int)p[e]; d = (int)p[N_EDGES + e];
    } else {
        const int* p = (const int*)ei;
        s = p[e]; d = p[N_EDGES + e];
    }
    if ((unsigned)s >= N_NODES) s = 0;
    if ((unsigned)d >= N_NODES) d = 0;
}

// ==================== CSR build ====================
__global__ void zero_counts_kernel(int* __restrict__ counts) {
    int i = blockIdx.x * blockDim.x + threadIdx.x;
    if (i < N_NODES) counts[i] = 0;
}
__global__ void count_kernel(const void* __restrict__ ei, int* __restrict__ counts) {
    __shared__ int sh64;
    if (threadIdx.x == 0) sh64 = probe64(ei);
    __syncthreads();
    int is64 = sh64;
    int e = blockIdx.x * blockDim.x + threadIdx.x;
    if (e < N_EDGES) {
        int s, d; load_edge(ei, is64, e, s, d);
        atomicAdd(&counts[d], 1);
    }
}
__global__ void scanA_kernel(const int* __restrict__ counts, int* __restrict__ offsets,
                             int* __restrict__ bsum) {
    __shared__ int wt[8];
    int tid = threadIdx.x, lane = tid & 31, wid = tid >> 5;
    int i = blockIdx.x * 256 + tid;
    int v = (i < N_NODES) ? counts[i] : 0;
    int x = v;
    #pragma unroll
    for (int o = 1; o < 32; o <<= 1) { int y = __shfl_up_sync(0xffffffffu, x, o); if (lane >= o) x += y; }
    if (lane == 31) wt[wid] = x;
    __syncthreads();
    if (wid == 0) {
        int s = (lane < 8) ? wt[lane] : 0;
        #pragma unroll
        for (int o = 1; o < 8; o <<= 1) { int y = __shfl_up_sync(0xffffffffu, s, o); if (lane >= o) s += y; }
        if (lane < 8) wt[lane] = s;
    }
    __syncthreads();
    int base = wid ? wt[wid - 1] : 0;
    if (i < N_NODES) offsets[i] = base + x - v;
    if (tid == 255) bsum[blockIdx.x] = base + x;
}
__global__ void scanB_kernel(int* __restrict__ bsum) {
    __shared__ int wt[8];
    int tid = threadIdx.x, lane = tid & 31, wid = tid >> 5;
    int v = (tid < SCAN_BLOCKS) ? bsum[tid] : 0;
    int x = v;
    #pragma unroll
    for (int o = 1; o < 32; o <<= 1) { int y = __shfl_up_sync(0xffffffffu, x, o); if (lane >= o) x += y; }
    if (lane == 31) wt[wid] = x;
    __syncthreads();
    if (wid == 0) {
        int s = (lane < 8) ? wt[lane] : 0;
        #pragma unroll
        for (int o = 1; o < 8; o <<= 1) { int y = __shfl_up_sync(0xffffffffu, s, o); if (lane >= o) s += y; }
        if (lane < 8) wt[lane] = s;
    }
    __syncthreads();
    int base = wid ? wt[wid - 1] : 0;
    if (tid < SCAN_BLOCKS) bsum[tid] = base + x - v;
}
__global__ void scanC_kernel(int* __restrict__ offsets, const int* __restrict__ bsum,
                             const int* __restrict__ counts, int* __restrict__ cursor,
                             float* __restrict__ dinv) {
    int i = blockIdx.x * 256 + threadIdx.x;
    if (i < N_NODES) {
        int off = offsets[i] + bsum[blockIdx.x];
        offsets[i] = off;
        cursor[i]  = off;
        dinv[i]    = rsqrtf((float)counts[i] + 1.0f);
    }
}
__global__ void scatter_kernel(const void* __restrict__ ei, int* __restrict__ cursor,
                               int* __restrict__ csr_src) {
    __shared__ int sh64;
    if (threadIdx.x == 0) sh64 = probe64(ei);
    __syncthreads();
    int is64 = sh64;
    int e = blockIdx.x * blockDim.x + threadIdx.x;
    if (e < N_EDGES) {
        int s, d; load_edge(ei, is64, e, s, d);
        int pos = atomicAdd(&cursor[d], 1);
        csr_src[pos] = s;
    }
}

// ==================== gather aggregation (warp per node, C=128) -> bf16 split ====
// out = sum_{src} dinv[s]*dinv[n]*feat[s] + dinv[n]^2*feat[n]  (+bias, relu if mode)
__global__ __launch_bounds__(256)
void gather_kernel(const int* __restrict__ csr_src, const int* __restrict__ offsets,
                   const int* __restrict__ counts, const float* __restrict__ dinv,
                   const float* __restrict__ feat, const float* __restrict__ bias,
                   __nv_bfloat16* __restrict__ outh, __nv_bfloat16* __restrict__ outl,
                   int mode) {
    int n = blockIdx.x * 8 + (threadIdx.x >> 5);
    if (n >= N_NODES) return;
    const int lane = threadIdx.x & 31;
    const int start = offsets[n];
    const int cnt   = counts[n];
    const float di  = dinv[n];
    const float4* base = (const float4*)feat;
    float4 acc;
    {
        float c = di * di;
        float4 v = base[(size_t)n * 32 + lane];
        acc = make_float4(v.x * c, v.y * c, v.z * c, v.w * c);
    }
    int e = 0;
    // unrolled x4: four independent 512B row loads in flight
    for (; e + 4 <= cnt; e += 4) {
        int sv = __ldg(&csr_src[start + e + (lane & 3)]);
        int s0 = __shfl_sync(0xffffffffu, sv, 0);
        int s1 = __shfl_sync(0xffffffffu, sv, 1);
        int s2 = __shfl_sync(0xffffffffu, sv, 2);
        int s3 = __shfl_sync(0xffffffffu, sv, 3);
        float c0 = __ldg(&dinv[s0]) * di;
        float c1 = __ldg(&dinv[s1]) * di;
        float c2 = __ldg(&dinv[s2]) * di;
        float c3 = __ldg(&dinv[s3]) * di;
        float4 v0 = __ldg(&base[(size_t)s0 * 32 + lane]);
        float4 v1 = __ldg(&base[(size_t)s1 * 32 + lane]);
        float4 v2 = __ldg(&base[(size_t)s2 * 32 + lane]);
        float4 v3 = __ldg(&base[(size_t)s3 * 32 + lane]);
        acc.x = fmaf(v0.x, c0, acc.x); acc.y = fmaf(v0.y, c0, acc.y);
        acc.z = fmaf(v0.z, c0, acc.z); acc.w = fmaf(v0.w, c0, acc.w);
        acc.x = fmaf(v1.x, c1, acc.x); acc.y = fmaf(v1.y, c1, acc.y);
        acc.z = fmaf(v1.z, c1, acc.z); acc.w = fmaf(v1.w, c1, acc.w);
        acc.x = fmaf(v2.x, c2, acc.x); acc.y = fmaf(v2.y, c2, acc.y);
        acc.z = fmaf(v2.z, c2, acc.z); acc.w = fmaf(v2.w, c2, acc.w);
        acc.x = fmaf(v3.x, c3, acc.x); acc.y = fmaf(v3.y, c3, acc.y);
        acc.z = fmaf(v3.z, c3, acc.z); acc.w = fmaf(v3.w, c3, acc.w);
    }
    for (; e < cnt; e++) {
        int s = __ldg(&csr_src[start + e]);
        float c = __ldg(&dinv[s]) * di;
        float4 v = __ldg(&base[(size_t)s * 32 + lane]);
        acc.x = fmaf(v.x, c, acc.x); acc.y = fmaf(v.y, c, acc.y);
        acc.z = fmaf(v.z, c, acc.z); acc.w = fmaf(v.w, c, acc.w);
    }
    if (mode) {
        float4 b = ((const float4*)bias)[lane];
        acc.x = fmaxf(acc.x + b.x, 0.f);
        acc.y = fmaxf(acc.y + b.y, 0.f);
        acc.z = fmaxf(acc.z + b.z, 0.f);
        acc.w = fmaxf(acc.w + b.w, 0.f);
    }
    __nv_bfloat16 h0, h1, h2, h3, l0, l1, l2, l3;
    split_bf16(acc.x, h0, l0); split_bf16(acc.y, h1, l1);
    split_bf16(acc.z, h2, l2); split_bf16(acc.w, h3, l3);
    uint32_t* oh = (uint32_t*)(outh + (size_t)n * 128 + lane * 4);
    uint32_t* ol = (uint32_t*)(outl + (size_t)n * 128 + lane * 4);
    oh[0] = pack_bf16x2(h0, h1); oh[1] = pack_bf16x2(h2, h3);
    ol[0] = pack_bf16x2(l0, l1); ol[1] = pack_bf16x2(l2, l3);
}

// ==================== fused weight transpose + split (all 4 weights) ====================
// segments: W1[128x256]->B1[256][128], W2[256x128]->B2[128][256], fcW1->B3, fcW2->B4
__global__ void wconv_all_kernel(const float* __restrict__ W1, const float* __restrict__ W2,
                                 const float* __restrict__ W3, const float* __restrict__ W4,
                                 __nv_bfloat16* __restrict__ B1h, __nv_bfloat16* __restrict__ B1l,
                                 __nv_bfloat16* __restrict__ B2h, __nv_bfloat16* __restrict__ B2l,
                                 __nv_bfloat16* __restrict__ B3h, __nv_bfloat16* __restrict__ B3l,
                                 __nv_bfloat16* __restrict__ B4h, __nv_bfloat16* __restrict__ B4l) {
    int idx = blockIdx.x * blockDim.x + threadIdx.x;  // 0..98303
    const float* W; __nv_bfloat16 *Bh, *Bl; int K, N, local;
    if (idx < 32768)      { W = W1; Bh = B1h; Bl = B1l; K = 128; N = 256; local = idx; }
    else if (idx < 65536) { W = W2; Bh = B2h; Bl = B2l; K = 256; N = 128; local = idx - 32768; }
    else if (idx < 81920) { W = W3; Bh = B3h; Bl = B3l; K = 128; N = 128; local = idx - 65536; }
    else if (idx < 98304) { W = W4; Bh = B4h; Bl = B4l; K = 128; N = 128; local = idx - 81920; }
    else return;
    int n = local / K, k = local - n * K;
    float w = W[(size_t)k * N + n];
    __nv_bfloat16 h, l;
    split_bf16(w, h, l);
    Bh[local] = h;
    Bl[local] = l;
}

// ==================== bf16-split GEMM via mma.sync (HMMA) ====================
#define PADK 40   // 32 + 8 bf16 pad: 80B row stride, conflict-free ldmatrix
template <int ACT, bool SPLIT_OUT>
__global__ void __launch_bounds__(256)
mma_gemm_kernel(const __nv_bfloat16* __restrict__ Ah, const __nv_bfloat16* __restrict__ Al,
                const __nv_bfloat16* __restrict__ Bh, const __nv_bfloat16* __restrict__ Bl,
                const float* __restrict__ bias,
                float* __restrict__ C, __nv_bfloat16* __restrict__ Ch,
                __nv_bfloat16* __restrict__ Cl, int M, int N, int K) {
    extern __shared__ char smem[];
    const uint32_t uAh = smem_u32(smem);
    const uint32_t uAl = uAh + 20480;
    const uint32_t uBh = uAl + 20480;
    const uint32_t uBl = uBh + 20480;

    const int tid  = threadIdx.x;
    const int lane = tid & 31;
    const int wid  = tid >> 5;
    const int wm   = wid & 3;
    const int wn   = wid >> 2;
    const int bn   = blockIdx.x * 128;
    const int bm   = blockIdx.y * 128;
    const int S    = K >> 5;

    float acc[2][8][4];
    #pragma unroll
    for (int i = 0; i < 2; i++)
        #pragma unroll
        for (int j = 0; j < 8; j++)
            #pragma unroll
            for (int q = 0; q < 4; q++) acc[i][j][q] = 0.f;

    const int c0   = tid * 2;
    const int row0 = c0 >> 2,  kc0v = (c0 & 3) * 8;
    const int kc1v = kc0v + 8;
    auto load_stage = [&](int s) {
        const int k0 = s * 32;
        const int buf = (s & 1) * 10240;
        const bool v0 = (bm + row0) < M;
        size_t aoff0 = (size_t)(v0 ? bm + row0 : 0) * K + k0;
        cp_async16(uAh + buf + (row0 * PADK + kc0v) * 2, Ah + aoff0 + kc0v, v0 ? 16 : 0);
        cp_async16(uAh + buf + (row0 * PADK + kc1v) * 2, Ah + aoff0 + kc1v, v0 ? 16 : 0);
        cp_async16(uAl + buf + (row0 * PADK + kc0v) * 2, Al + aoff0 + kc0v, v0 ? 16 : 0);
        cp_async16(uAl + buf + (row0 * PADK + kc1v) * 2, Al + aoff0 + kc1v, v0 ? 16 : 0);
        size_t boff0 = (size_t)(bn + row0) * K + k0;
        cp_async16(uBh + buf + (row0 * PADK + kc0v) * 2, Bh + boff0 + kc0v, 16);
        cp_async16(uBh + buf + (row0 * PADK + kc1v) * 2, Bh + boff0 + kc1v, 16);
        cp_async16(uBl + buf + (row0 * PADK + kc0v) * 2, Bl + boff0 + kc0v, 16);
        cp_async16(uBl + buf + (row0 * PADK + kc1v) * 2, Bl + boff0 + kc1v, 16);
    };

    const int a_r = wm * 32 + (lane & 15);
    const int a_c = (lane >> 4) * 8;
    const int bj  = lane >> 3;
    const int b_r = wn * 64 + ((bj >> 1) << 3) + (lane & 7);
    const int b_c = (bj & 1) << 3;

    load_stage(0);
    CP_COMMIT();
    for (int s = 0; s < S; s++) {
        if (s + 1 < S) { load_stage(s + 1); CP_COMMIT(); cp_wait<1>(); }
        else cp_wait<0>();
        __syncthreads();
        const int buf = (s & 1) * 10240;
        #pragma unroll
        for (int k16 = 0; k16 < 32; k16 += 16) {
            uint32_t aH[2][4], aL[2][4], bH[8][2];
            #pragma unroll
            for (int f = 0; f < 2; f++) {
                ldsm_x4(aH[f], uAh + buf + ((a_r + f * 16) * PADK + k16 + a_c) * 2);
                ldsm_x4(aL[f], uAl + buf + ((a_r + f * 16) * PADK + k16 + a_c) * 2);
            }
            #pragma unroll
            for (int nf = 0; nf < 4; nf++) {
                uint32_t r[4];
                ldsm_x4(r, uBh + buf + ((b_r + nf * 16) * PADK + k16 + b_c) * 2);
                bH[nf * 2][0] = r[0]; bH[nf * 2][1] = r[1];
                bH[nf * 2 + 1][0] = r[2]; bH[nf * 2 + 1][1] = r[3];
            }
            #pragma unroll
            for (int mi = 0; mi < 2; mi++)
                #pragma unroll
                for (int ni = 0; ni < 8; ni++) {
                    mma16816(acc[mi][ni], aH[mi], bH[ni]);
                    mma16816(acc[mi][ni], aL[mi], bH[ni]);
                }
            #pragma unroll
            for (int nf = 0; nf < 4; nf++) {
                uint32_t r[4];
                ldsm_x4(r, uBl + buf + ((b_r + nf * 16) * PADK + k16 + b_c) * 2);
                bH[nf * 2][0] = r[0]; bH[nf * 2][1] = r[1];
                bH[nf * 2 + 1][0] = r[2]; bH[nf * 2 + 1][1] = r[3];
            }
            #pragma unroll
            for (int mi = 0; mi < 2; mi++)
                #pragma unroll
                for (int ni = 0; ni < 8; ni++)
                    mma16816(acc[mi][ni], aH[mi], bH[ni]);
        }
        __syncthreads();
    }

    const int g = lane >> 2, tig = lane & 3;
    float bb[8][2];
    if (ACT != 0) {
        #pragma unroll
        for (int ni = 0; ni < 8; ni++) {
            int col = bn + wn * 64 + ni * 8 + tig * 2;
            bb[ni][0] = bias[col];
            bb[ni][1] = bias[col + 1];
        }
    }
    #pragma unroll
    for (int mi = 0; mi < 2; mi++) {
        int r0 = bm + wm * 32 + mi * 16 + g;
        #pragma unroll
        for (int half = 0; half < 2; half++) {
            int row = r0 + half * 8;
            if (row >= M) continue;
            #pragma unroll
            for (int ni = 0; ni < 8; ni++) {
                int col = bn + wn * 64 + ni * 8 + tig * 2;
                float v0 = acc[mi][ni][half * 2 + 0];
                float v1 = acc[mi][ni][half * 2 + 1];
                if (ACT != 0) { v0 += bb[ni][0]; v1 += bb[ni][1]; }
                if (ACT == 1) { v0 = fmaxf(v0, 0.f); v1 = fmaxf(v1, 0.f); }
                if (ACT == 2) {
                    v0 = v0 > 0.f ? v0 : expm1f(v0);
                    v1 = v1 > 0.f ? v1 : expm1f(v1);
                }
                if (SPLIT_OUT) {
                    __nv_bfloat16 h0, l0, h1, l1;
                    split_bf16(v0, h0, l0); split_bf16(v1, h1, l1);
                    *(uint32_t*)(Ch + (size_t)row * N + col) = pack_bf16x2(h0, h1);
                    *(uint32_t*)(Cl + (size_t)row * N + col) = pack_bf16x2(l0, l1);
                } else {
                    *(float2*)(C + (size_t)row * N + col) = make_float2(v0, v1);
                }
            }
        }
    }
}

// ==================== fused projection head ====================
// out = elu(Z @ fcW1 + fcb1) @ fcW2 + fcb2, all dims 128; p-tile stays in SMEM.
#define PT 136   // resident-tile k-stride (272B rows; 272/16=17 odd -> conflict-free)
__global__ void __launch_bounds__(256)
proj_fused_kernel(const __nv_bfloat16* __restrict__ Zh, const __nv_bfloat16* __restrict__ Zl,
                  const __nv_bfloat16* __restrict__ B3h, const __nv_bfloat16* __restrict__ B3l,
                  const __nv_bfloat16* __restrict__ B4h, const __nv_bfloat16* __restrict__ B4l,
                  const float* __restrict__ fcb1, const float* __restrict__ fcb2,
                  float* __restrict__ out, int M) {
    extern __shared__ char smem[];
    const uint32_t uAh = smem_u32(smem);         // pipeline regions (phase 1)
    const uint32_t uAl = uAh + 20480;
    const uint32_t uBh = uAl + 20480;
    const uint32_t uBl = uBh + 20480;
    const uint32_t uPTH = uAh + 81920;           // p-tile hi [128][PT]
    const uint32_t uPTL = uPTH + 34816;          // p-tile lo
    // phase-2 weight regions (reuse freed pipeline space)
    const uint32_t uW4h = uAh;                   // [128][PT] = 34816 <= 40960
    const uint32_t uW4l = uBh;

    const int tid  = threadIdx.x;
    const int lane = tid & 31;
    const int wid  = tid >> 5;
    const int wm   = wid & 3;
    const int wn   = wid >> 2;
    const int bm   = blockIdx.x * 128;
    const int K    = 128;
    const int S    = K >> 5;   // 4 stages

    float acc[2][8][4];
    #pragma unroll
    for (int i = 0; i < 2; i++)
        #pragma unroll
        for (int j = 0; j < 8; j++)
            #pragma unroll
            for (int q = 0; q < 4; q++) acc[i][j][q] = 0.f;

    const int c0   = tid * 2;
    const int row0 = c0 >> 2,  kc0v = (c0 & 3) * 8;
    const int kc1v = kc0v + 8;
    auto load_stage = [&](int s) {
        const int k0 = s * 32;
        const int buf = (s & 1) * 10240;
        const bool v0 = (bm + row0) < M;
        size_t aoff0 = (size_t)(v0 ? bm + row0 : 0) * K + k0;
        cp_async16(uAh + buf + (row0 * PADK + kc0v) * 2, Zh + aoff0 + kc0v, v0 ? 16 : 0);
        cp_async16(uAh + buf + (row0 * PADK + kc1v) * 2, Zh + aoff0 + kc1v, v0 ? 16 : 0);
        cp_async16(uAl + buf + (row0 * PADK + kc0v) * 2, Zl + aoff0 + kc0v, v0 ? 16 : 0);
        cp_async16(uAl + buf + (row0 * PADK + kc1v) * 2, Zl + aoff0 + kc1v, v0 ? 16 : 0);
        size_t boff0 = (size_t)row0 * K + k0;
        cp_async16(uBh + buf + (row0 * PADK + kc0v) * 2, B3h + boff0 + kc0v, 16);
        cp_async16(uBh + buf + (row0 * PADK + kc1v) * 2, B3h + boff0 + kc1v, 16);
        cp_async16(uBl + buf + (row0 * PADK + kc0v) * 2, B3l + boff0 + kc0v, 16);
        cp_async16(uBl + buf + (row0 * PADK + kc1v) * 2, B3l + boff0 + kc1v, 16);
    };

    const int a_r = wm * 32 + (lane & 15);
    const int a_c = (lane >> 4) * 8;
    const int bj  = lane >> 3;
    const int b_r = wn * 64 + ((bj >> 1) << 3) + (lane & 7);
    const int b_c = (bj & 1) << 3;

    // ---- phase 1 mainloop: acc = Z @ fcW1 (split 3-term)
    load_stage(0);
    CP_COMMIT();
    for (int s = 0; s < S; s++) {
        if (s + 1 < S) { load_stage(s + 1); CP_COMMIT(); cp_wait<1>(); }
        else cp_wait<0>();
        __syncthreads();
        const int buf = (s & 1) * 10240;
        #pragma unroll
        for (int k16 = 0; k16 < 32; k16 += 16) {
            uint32_t aH[2][4], aL[2][4], bH[8][2];
            #pragma unroll
            for (int f = 0; f < 2; f++) {
                ldsm_x4(aH[f], uAh + buf + ((a_r + f * 16) * PADK + k16 + a_c) * 2);
                ldsm_x4(aL[f], uAl + buf + ((a_r + f * 16) * PADK + k16 + a_c) * 2);
            }
            #pragma unroll
            for (int nf = 0; nf < 4; nf++) {
                uint32_t r[4];
                ldsm_x4(r, uBh + buf + ((b_r + nf * 16) * PADK + k16 + b_c) * 2);
                bH[nf * 2][0] = r[0]; bH[nf * 2][1] = r[1];
                bH[nf * 2 + 1][0] = r[2]; bH[nf * 2 + 1][1] = r[3];
            }
            #pragma unroll
            for (int mi = 0; mi < 2; mi++)
                #pragma unroll
                for (int ni = 0; ni < 8; ni++) {
                    mma16816(acc[mi][ni], aH[mi], bH[ni]);
                    mma16816(acc[mi][ni], aL[mi], bH[ni]);
                }
            #pragma unroll
            for (int nf = 0; nf < 4; nf++) {
                uint32_t r[4];
                ldsm_x4(r, uBl + buf + ((b_r + nf * 16) * PADK + k16 + b_c) * 2);
                bH[nf * 2][0] = r[0]; bH[nf * 2][1] = r[1];
                bH[nf * 2 + 1][0] = r[2]; bH[nf * 2 + 1][1] = r[3];
            }
            #pragma unroll
            for (int mi = 0; mi < 2; mi++)
                #pragma unroll
                for (int ni = 0; ni < 8; ni++)
                    mma16816(acc[mi][ni], aH[mi], bH[ni]);
        }
        __syncthreads();
    }

    // ---- epilogue 1: bias+elu, split -> SMEM p-tile
    {
        const int g = lane >> 2, tig = lane & 3;
        #pragma unroll
        for (int mi = 0; mi < 2; mi++) {
            int lr0 = wm * 32 + mi * 16 + g;
            #pragma unroll
            for (int half = 0; half < 2; half++) {
                int lr = lr0 + half * 8;
                #pragma unroll
                for (int ni = 0; ni < 8; ni++) {
                    int col = wn * 64 + ni * 8 + tig * 2;
                    float v0 = acc[mi][ni][half * 2 + 0] + fcb1[col];
                    float v1 = acc[mi][ni][half * 2 + 1] + fcb1[col + 1];
                    v0 = v0 > 0.f ? v0 : expm1f(v0);
                    v1 = v1 > 0.f ? v1 : expm1f(v1);
                    __nv_bfloat16 h0, l0, h1, l1;
                    split_bf16(v0, h0, l0); split_bf16(v1, h1, l1);
                    *(uint32_t*)((char*)smem + (uPTH - uAh) + (lr * PT + col) * 2) = pack_bf16x2(h0, h1);
                    *(uint32_t*)((char*)smem + (uPTL - uAh) + (lr * PT + col) * 2) = pack_bf16x2(l0, l1);
                }
            }
        }
    }
    // ---- load fcW2 split into freed pipeline regions
    for (int u = tid; u < 128 * 16; u += 256) {   // 2048 x 16B chunks per matrix
        int r = u >> 4, kc = (u & 15) * 8;
        *(uint4*)((char*)smem + (uW4h - uAh) + (r * PT + kc) * 2) = *(const uint4*)(B4h + (size_t)r * 128 + kc);
        *(uint4*)((char*)smem + (uW4l - uAh) + (r * PT + kc) * 2) = *(const uint4*)(B4l + (size_t)r * 128 + kc);
    }
    __syncthreads();

    // ---- phase 2 mainloop: out = P @ fcW2 (split 3-term), all operands SMEM-resident
    #pragma unroll
    for (int i = 0; i < 2; i++)
        #pragma unroll
        for (int j = 0; j < 8; j++)
            #pragma unroll
            for (int q = 0; q < 4; q++) acc[i][j][q] = 0.f;
    #pragma unroll
    for (int k16 = 0; k16 < 128; k16 += 16) {
        uint32_t aH[2][4], aL[2][4], bH[8][2];
        #pragma unroll
        for (int f = 0; f < 2; f++) {
            ldsm_x4(aH[f], uPTH + ((a_r + f * 16) * PT + k16 + a_c) * 2);
            ldsm_x4(aL[f], uPTL + ((a_r + f * 16) * PT + k16 + a_c) * 2);
        }
        #pragma unroll
        for (int nf = 0; nf < 4; nf++) {
            uint32_t r[4];
            ldsm_x4(r, uW4h + ((b_r + nf * 16) * PT + k16 + b_c) * 2);
            bH[nf * 2][0] = r[0]; bH[nf * 2][1] = r[1];
            bH[nf * 2 + 1][0] = r[2]; bH[nf * 2 + 1][1] = r[3];
        }
        #pragma unroll
        for (int mi = 0; mi < 2; mi++)
            #pragma unroll
            for (int ni = 0; ni < 8; ni++) {
                mma16816(acc[mi][ni], aH[mi], bH[ni]);
                mma16816(acc[mi][ni], aL[mi], bH[ni]);
            }
        #pragma unroll
        for (int nf = 0; nf < 4; nf++) {
            uint32_t r[4];
            ldsm_x4(r, uW4l + ((b_r + nf * 16) * PT + k16 + b_c) * 2);
            bH[nf * 2][0] = r[0]; bH[nf * 2][1] = r[1];
            bH[nf * 2 + 1][0] = r[2]; bH[nf * 2 + 1][1] = r[3];
        }
        #pragma unroll
        for (int mi = 0; mi < 2; mi++)
            #pragma unroll
            for (int ni = 0; ni < 8; ni++)
                mma16816(acc[mi][ni], aH[mi], bH[ni]);
    }

    // ---- epilogue 2: + fcb2, fp32 out
    {
        const int g = lane >> 2, tig = lane & 3;
        #pragma unroll
        for (int mi = 0; mi < 2; mi++) {
            int r0 = bm + wm * 32 + mi * 16 + g;
            #pragma unroll
            for (int half = 0; half < 2; half++) {
                int row = r0 + half * 8;
                if (row >= M) continue;
                #pragma unroll
                for (int ni = 0; ni < 8; ni++) {
                    int col = wn * 64 + ni * 8 + tig * 2;
                    float v0 = acc[mi][ni][half * 2 + 0] + fcb2[col];
                    float v1 = acc[mi][ni][half * 2 + 1] + fcb2[col + 1];
                    *(float2*)(out + (size_t)row * 128 + col) = make_float2(v0, v1);
                }
            }
        }
    }
}

// ==================== launch ====================
extern "C" void kernel_launch(void* const* d_in, const int* in_sizes, int n_in,
                              void* d_out, int out_size) {
    const float* x    = (const float*)d_in[0];
    const void*  ei   = d_in[1];
    const float* W1   = (const float*)d_in[2];
    const float* b1   = (const float*)d_in[3];
    const float* W2   = (const float*)d_in[4];
    const float* b2   = (const float*)d_in[5];
    const float* fcW1 = (const float*)d_in[6];
    const float* fcb1 = (const float*)d_in[7];
    const float* fcW2 = (const float*)d_in[8];
    const float* fcb2 = (const float*)d_in[9];
    float* out = (float*)d_out;

    int *counts, *offsets, *cursor, *csr_src, *bsum;
    float *dinv, *xw2;
    __nv_bfloat16 *p1h, *p1l, *p2h, *p2l;
    __nv_bfloat16 *B1h, *B1l, *B2h, *B2l, *B3h, *B3l, *B4h, *B4l;
    cudaGetSymbolAddress((void**)&counts,  g_counts);
    cudaGetSymbolAddress((void**)&offsets, g_offsets);
    cudaGetSymbolAddress((void**)&cursor,  g_cursor);
    cudaGetSymbolAddress((void**)&csr_src, g_csr_src);
    cudaGetSymbolAddress((void**)&bsum,    g_bsum);
    cudaGetSymbolAddress((void**)&dinv,    g_dinv);
    cudaGetSymbolAddress((void**)&xw2,     g_xw2);
    cudaGetSymbolAddress((void**)&p1h,     g_p1h);
    cudaGetSymbolAddress((void**)&p1l,     g_p1l);
    cudaGetSymbolAddress((void**)&p2h,     g_p2h);
    cudaGetSymbolAddress((void**)&p2l,     g_p2l);
    cudaGetSymbolAddress((void**)&B1h,     g_B1h);
    cudaGetSymbolAddress((void**)&B1l,     g_B1l);
    cudaGetSymbolAddress((void**)&B2h,     g_B2h);
    cudaGetSymbolAddress((void**)&B2l,     g_B2l);
    cudaGetSymbolAddress((void**)&B3h,     g_B3h);
    cudaGetSymbolAddress((void**)&B3l,     g_B3l);
    cudaGetSymbolAddress((void**)&B4h,     g_B4h);
    cudaGetSymbolAddress((void**)&B4l,     g_B4l);

    const int EB  = (N_EDGES + 255) / 256;
    const int GB  = (N_NODES + 7) / 8;
    const int MBY = (N_NODES + 127) / 128;    // 391
    constexpr int GSMEM = 4 * 20480;          // 81920
    constexpr int PSMEM = 81920 + 2 * 34816;  // 151552

    cudaFuncSetAttribute(mma_gemm_kernel<1, true>,  cudaFuncAttributeMaxDynamicSharedMemorySize, GSMEM);
    cudaFuncSetAttribute(mma_gemm_kernel<0, false>, cudaFuncAttributeMaxDynamicSharedMemorySize, GSMEM);
    cudaFuncSetAttribute(proj_fused_kernel, cudaFuncAttributeMaxDynamicSharedMemorySize, PSMEM);

    // ---- CSR build + dinv
    zero_counts_kernel<<<SCAN_BLOCKS, 256>>>(counts);
    count_kernel<<<EB, 256>>>(ei, counts);
    scanA_kernel<<<SCAN_BLOCKS, 256>>>(counts, offsets, bsum);
    scanB_kernel<<<1, 256>>>(bsum);
    scanC_kernel<<<SCAN_BLOCKS, 256>>>(offsets, bsum, counts, cursor, dinv);
    scatter_kernel<<<EB, 256>>>(ei, cursor, csr_src);

    // ---- layer 1: aggx = A_hat @ x (split) ; h = relu(aggx @ W1 + b1) (split)
    gather_kernel<<<GB, 256>>>(csr_src, offsets, counts, dinv, x, nullptr, p1h, p1l, 0);
    wconv_all_kernel<<<384, 256>>>(W1, W2, fcW1, fcW2, B1h, B1l, B2h, B2l, B3h, B3l, B4h, B4l);
    {
        dim3 grid(C1 / 128, MBY);
        mma_gemm_kernel<1, true><<<grid, 256, GSMEM>>>(p1h, p1l, B1h, B1l, b1,
                                                       nullptr, p2h, p2l, N_NODES, C1, C2);
    }

    // ---- layer 2: xw2 = h @ W2 (fp32) ; z = relu(A_hat @ xw2 + b2) (split)
    {
        dim3 grid(C2 / 128, MBY);
        mma_gemm_kernel<0, false><<<grid, 256, GSMEM>>>(p2h, p2l, B2h, B2l, nullptr,
                                                        xw2, nullptr, nullptr, N_NODES, C2, C1);
    }
    gather_kernel<<<GB, 256>>>(csr_src, offsets, counts, dinv, xw2, b2, p1h, p1l, 1);

    // ---- fused projection head
    proj_fused_kernel<<<MBY, 256, PSMEM>>>(p1h, p1l, B3h, B3l, B4h, B4l, fcb1, fcb2, out, N_NODES);
}